// round 2
// baseline (speedup 1.0000x reference)
#include <cuda_runtime.h>
#include <math.h>
#include <stdint.h>

// Problem constants
#define S_LEN 128
#define BATCH 64
#define HID   1024
#define VOCAB 10000
#define SB    8192            // S_LEN*BATCH
#define ROWH  65536           // BATCH*HID (one timestep slab)
#define LOGITS_ELEMS 81920000 // SB*VOCAB
#define HIDFIN_ELEMS 131072   // 2*BATCH*HID

typedef unsigned long long ull;

// ---------------- scratch (static device memory; no allocation) -------------
__device__ float g_X[SB * HID];        // Xp0, later Xp1
__device__ float g_H[SB * HID];        // H0[t], later TOP[t]
__device__ float g_WhT[2 * HID * HID]; // transposed Wh per layer
__device__ float g_hf0[ROWH];          // layer-0 final hidden
__device__ unsigned g_cnt;
__device__ unsigned g_rel;

// ---------------- f32x2 helpers ---------------------------------------------
__device__ __forceinline__ ull pk(float x, float y) {
    ull r; asm("mov.b64 %0, {%1, %2};" : "=l"(r) : "f"(x), "f"(y)); return r;
}
__device__ __forceinline__ float2 up(ull v) {
    float2 r; asm("mov.b64 {%0, %1}, %2;" : "=f"(r.x), "=f"(r.y) : "l"(v)); return r;
}
__device__ __forceinline__ ull fma2(ull a, ull b, ull c) {
    ull d; asm("fma.rn.f32x2 %0, %1, %2, %3;" : "=l"(d) : "l"(a), "l"(b), "l"(c)); return d;
}

// ---------------- init ------------------------------------------------------
__global__ void k_init() { g_cnt = 0; g_rel = 0; }

// ---------------- Wh transpose: WhT[l][j][k] = Wh[l][k][j] ------------------
__global__ void k_transpose(const float* __restrict__ src, float* __restrict__ dst) {
    __shared__ float tile[32][33];
    int l = blockIdx.z;
    const float* s = src + (size_t)l * (HID * HID);
    float* d = dst + (size_t)l * (HID * HID);
    int x = blockIdx.x * 32 + threadIdx.x;   // j
    int y0 = blockIdx.y * 32;                // k base
    #pragma unroll
    for (int r = threadIdx.y; r < 32; r += 8)
        tile[r][threadIdx.x] = s[(size_t)(y0 + r) * HID + x];
    __syncthreads();
    int xo = y0 + threadIdx.x;               // k
    int yo0 = blockIdx.x * 32;               // j base
    #pragma unroll
    for (int r = threadIdx.y; r < 32; r += 8)
        d[(size_t)(yo0 + r) * HID + xo] = tile[threadIdx.x][r];
}

// ---------------- generic SGEMM: C[M,N] = A[M,1024] @ B[1024,N] + bias ------
// A rows optionally gathered via idx (embedding). M % 128 == 0, K == 1024.
__global__ __launch_bounds__(256, 2)
void k_sgemm(const float* __restrict__ A, const int* __restrict__ idx,
             const float* __restrict__ B, const float* __restrict__ bias,
             float* __restrict__ C, int M, int N) {
    __shared__ __align__(16) ull   As2[2][16][128]; // dup-packed A: {a,a}
    __shared__ __align__(16) float Bs[2][16][128];

    const int tid = threadIdx.x;
    const int bx = blockIdx.x, by = blockIdx.y;

    // A loader: thread -> (row lm, k-half kh)
    const int lm = tid >> 1, kh = (tid & 1) << 3;
    const int i = by * 128 + lm;
    const float* arow = idx ? (A + (size_t)idx[i] * HID) : (A + (size_t)i * HID);

    // B loader: thread -> (k row bk / bk+8, 4 cols at bn)
    const int bk = tid >> 5, bn = (tid & 31) << 2;
    const int bcol = bx * 128 + bn;

    // compute mapping
    const int ty = tid >> 4, tx = tid & 15;
    const int m0 = ty << 3, n0 = tx << 3;

    ull acc[8][4];
    #pragma unroll
    for (int m = 0; m < 8; m++)
        #pragma unroll
        for (int n = 0; n < 4; n++) acc[m][n] = 0ULL;

    float4 ra0, ra1, rb0, rb1;

#define LOADTILE(KB)                                                          \
    {                                                                         \
        ra0 = *(const float4*)(arow + (KB) + kh);                             \
        ra1 = *(const float4*)(arow + (KB) + kh + 4);                         \
        if (bcol < N) {                                                       \
            rb0 = *(const float4*)(B + (size_t)((KB) + bk) * N + bcol);       \
            rb1 = *(const float4*)(B + (size_t)((KB) + bk + 8) * N + bcol);   \
        } else {                                                              \
            rb0 = make_float4(0.f, 0.f, 0.f, 0.f);                            \
            rb1 = make_float4(0.f, 0.f, 0.f, 0.f);                            \
        }                                                                     \
    }

#define STORETILE(BUF)                                                        \
    {                                                                         \
        As2[BUF][kh + 0][lm] = pk(ra0.x, ra0.x);                              \
        As2[BUF][kh + 1][lm] = pk(ra0.y, ra0.y);                              \
        As2[BUF][kh + 2][lm] = pk(ra0.z, ra0.z);                              \
        As2[BUF][kh + 3][lm] = pk(ra0.w, ra0.w);                              \
        As2[BUF][kh + 4][lm] = pk(ra1.x, ra1.x);                              \
        As2[BUF][kh + 5][lm] = pk(ra1.y, ra1.y);                              \
        As2[BUF][kh + 6][lm] = pk(ra1.z, ra1.z);                              \
        As2[BUF][kh + 7][lm] = pk(ra1.w, ra1.w);                              \
        *(float4*)&Bs[BUF][bk][bn]     = rb0;                                 \
        *(float4*)&Bs[BUF][bk + 8][bn] = rb1;                                 \
    }

    LOADTILE(0);
    STORETILE(0);
    __syncthreads();

    const int NKT = HID / 16; // 64
    for (int kt = 0; kt < NKT; kt++) {
        const int buf = kt & 1;
        if (kt + 1 < NKT) LOADTILE((kt + 1) * 16);

        #pragma unroll
        for (int k = 0; k < 16; k++) {
            const ulonglong2* ap = (const ulonglong2*)&As2[buf][k][m0];
            ulonglong2 a01 = ap[0], a23 = ap[1], a45 = ap[2], a67 = ap[3];
            const ulonglong2* bp = (const ulonglong2*)&Bs[buf][k][n0];
            ulonglong2 b01 = bp[0], b23 = bp[1];
            ull av[8] = {a01.x, a01.y, a23.x, a23.y, a45.x, a45.y, a67.x, a67.y};
            ull bv[4] = {b01.x, b01.y, b23.x, b23.y};
            #pragma unroll
            for (int m = 0; m < 8; m++)
                #pragma unroll
                for (int n = 0; n < 4; n++)
                    acc[m][n] = fma2(av[m], bv[n], acc[m][n]);
        }

        if (kt + 1 < NKT) {
            __syncthreads();
            STORETILE(buf ^ 1);
            __syncthreads();
        }
    }

    // epilogue: bias + store (N is even; pairs are fully in or fully out)
    float2 bb[4];
    #pragma unroll
    for (int np = 0; np < 4; np++) {
        int c = bx * 128 + n0 + 2 * np;
        bb[np] = (c < N) ? *(const float2*)(bias + c) : make_float2(0.f, 0.f);
    }
    #pragma unroll
    for (int m = 0; m < 8; m++) {
        size_t rowC = (size_t)(by * 128 + m0 + m) * N;
        #pragma unroll
        for (int np = 0; np < 4; np++) {
            int c = bx * 128 + n0 + 2 * np;
            if (c < N) {
                float2 v = up(acc[m][np]);
                v.x += bb[np].x; v.y += bb[np].y;
                *(float2*)(C + rowC + c) = v;
            }
        }
    }
#undef LOADTILE
#undef STORETILE
}

// ---------------- grid barrier (128 co-resident blocks) ---------------------
__device__ __forceinline__ void grid_barrier(unsigned rv) {
    __syncthreads();
    if (threadIdx.x == 0) {
        __threadfence();
        unsigned prev = atomicAdd(&g_cnt, 1);
        if (prev == gridDim.x - 1) {
            atomicExch(&g_cnt, 0);
            __threadfence();
            asm volatile("st.release.gpu.u32 [%0], %1;" :: "l"(&g_rel), "r"(rv) : "memory");
        } else {
            unsigned v;
            do {
                asm volatile("ld.acquire.gpu.u32 %0, [%1];" : "=r"(v) : "l"(&g_rel) : "memory");
            } while (v < rv);
        }
    }
    __syncthreads();
}

// ---------------- recurrent scan (one layer): persistent, 128 blocks --------
// step t: H[t] = tanh( Xp[t] + H[t-1] @ Wh )   (WT = Wh^T, rows = output col)
__global__ __launch_bounds__(128)
void k_scan(const float* __restrict__ Xp, float* __restrict__ Hbuf,
            const float* __restrict__ WT, const float* __restrict__ hinit,
            float* __restrict__ finalOut, unsigned epoch0) {
    const int tid = threadIdx.x;
    const int jb = blockIdx.x * 8;
    const int r2 = tid >> 2, c2 = tid & 3;
    const int r0 = r2 << 1;
    const int j0 = jb + (c2 << 1);
    const float* w0p = WT + (size_t)j0 * HID;
    const float* w1p = w0p + HID;

    for (int t = 0; t < S_LEN; t++) {
        const float* Hp = t ? (Hbuf + (size_t)(t - 1) * ROWH) : hinit;
        const float* h0p = Hp + (size_t)r0 * HID;
        const float* h1p = h0p + HID;

        ull a00 = 0, a01 = 0, a10 = 0, a11 = 0;
        #pragma unroll 4
        for (int k = 0; k < HID; k += 4) {
            ulonglong2 ha = *(const ulonglong2*)(h0p + k);
            ulonglong2 hb = *(const ulonglong2*)(h1p + k);
            ulonglong2 wa = *(const ulonglong2*)(w0p + k);
            ulonglong2 wb = *(const ulonglong2*)(w1p + k);
            a00 = fma2(ha.x, wa.x, a00); a00 = fma2(ha.y, wa.y, a00);
            a01 = fma2(ha.x, wb.x, a01); a01 = fma2(ha.y, wb.y, a01);
            a10 = fma2(hb.x, wa.x, a10); a10 = fma2(hb.y, wa.y, a10);
            a11 = fma2(hb.x, wb.x, a11); a11 = fma2(hb.y, wb.y, a11);
        }
        float2 s00 = up(a00), s01 = up(a01), s10 = up(a10), s11 = up(a11);

        size_t xb = (size_t)t * ROWH + (size_t)r0 * HID + j0;
        float2 x0 = *(const float2*)(Xp + xb);
        float2 x1 = *(const float2*)(Xp + xb + HID);

        float h00 = tanhf(x0.x + s00.x + s00.y);
        float h01 = tanhf(x0.y + s01.x + s01.y);
        float h10 = tanhf(x1.x + s10.x + s10.y);
        float h11 = tanhf(x1.y + s11.x + s11.y);

        *(float2*)(Hbuf + xb)        = make_float2(h00, h01);
        *(float2*)(Hbuf + xb + HID)  = make_float2(h10, h11);

        if (t == S_LEN - 1 && finalOut) {
            size_t fb = (size_t)r0 * HID + j0;
            *(float2*)(finalOut + fb)       = make_float2(h00, h01);
            *(float2*)(finalOut + fb + HID) = make_float2(h10, h11);
        }
        grid_barrier(epoch0 + (unsigned)t + 1);
    }
}

// ---------------- hidden_final epilogue -------------------------------------
__global__ void k_final(float* __restrict__ out) {
    int i = blockIdx.x * blockDim.x + threadIdx.x;
    if (i < ROWH) {
        out[LOGITS_ELEMS + i]        = g_hf0[i];
        out[LOGITS_ELEMS + ROWH + i] = g_H[(size_t)(S_LEN - 1) * ROWH + i];
    }
}

// ---------------- launcher ---------------------------------------------------
extern "C" void kernel_launch(void* const* d_in, const int* in_sizes, int n_in,
                              void* d_out, int out_size) {
    const int*   inputs = (const int*)d_in[0];
    const float* hidden = (const float*)d_in[1];
    const float* emb    = (const float*)d_in[2];
    const float* Wx     = (const float*)d_in[3];
    const float* Wh     = (const float*)d_in[4];
    const float* b      = (const float*)d_in[5];
    const float* Wo     = (const float*)d_in[6];
    const float* bo     = (const float*)d_in[7];
    float* out = (float*)d_out;

    float *pX = 0, *pH = 0, *pWT = 0, *phf = 0;
    cudaGetSymbolAddress((void**)&pX,  g_X);
    cudaGetSymbolAddress((void**)&pH,  g_H);
    cudaGetSymbolAddress((void**)&pWT, g_WhT);
    cudaGetSymbolAddress((void**)&phf, g_hf0);

    k_init<<<1, 1>>>();
    k_transpose<<<dim3(32, 32, 2), dim3(32, 8)>>>(Wh, pWT);

    // Xp0 = emb[inputs] @ Wx0 + b0
    k_sgemm<<<dim3(8, 64), 256>>>(emb, inputs, Wx, b, pX, SB, HID);
    // h0 scan
    k_scan<<<128, 128>>>(pX, pH, pWT, hidden, phf, 0u);
    // Xp1 = H0 @ Wx1 + b1
    k_sgemm<<<dim3(8, 64), 256>>>(pH, nullptr, Wx + HID * HID, b + HID, pX, SB, HID);
    // h1 scan (state ping-pongs inside g_H; becomes TOP)
    k_scan<<<128, 128>>>(pX, pH, pWT + HID * HID, hidden + ROWH, nullptr, 128u);
    // logits = TOP @ Wo + bo
    k_sgemm<<<dim3(79, 64), 256>>>(pH, nullptr, Wo, bo, out, SB, VOCAB);

    if (out_size >= LOGITS_ELEMS + HIDFIN_ELEMS)
        k_final<<<128, 512>>>(out);
}

// round 4
// speedup vs baseline: 1.1638x; 1.1638x over previous
#include <cuda_runtime.h>
#include <cuda_bf16.h>
#include <math.h>
#include <stdint.h>

// Problem constants
#define S_LEN 128
#define BATCH 64
#define HID   1024
#define VOCAB 10000
#define VPAD  10240
#define SB    8192
#define ROWH  65536
#define LOGITS_ELEMS 81920000
#define HIDFIN_ELEMS 131072
#define KPACK 2048               // [hi(1024) | lo(1024)] bf16 per row

typedef unsigned long long ull;

// ---------------- static scratch ------------------------------------------
__device__ float g_X[SB * HID];                       // Xp (fp32)
__device__ float g_H[SB * HID];                       // H states (fp32)
__device__ float g_WhT[2 * HID * HID];                // Wh^T fp32 (scan)
__device__ float g_hf0[ROWH];                         // layer-0 final hidden
__device__ __nv_bfloat16 g_A2[(size_t)SB * KPACK];    // split A
__device__ __nv_bfloat16 g_WoT2[(size_t)VPAD * KPACK];// split Wo^T (padded)
__device__ __nv_bfloat16 g_WxT2[2 * HID * KPACK];     // split Wx^T per layer
__device__ unsigned g_cnt, g_rel;

// ---------------- f32x2 helpers (scan) ------------------------------------
__device__ __forceinline__ float2 up(ull v) {
    float2 r; asm("mov.b64 {%0, %1}, %2;" : "=f"(r.x), "=f"(r.y) : "l"(v)); return r;
}
__device__ __forceinline__ ull fma2(ull a, ull b, ull c) {
    ull d; asm("fma.rn.f32x2 %0, %1, %2, %3;" : "=l"(d) : "l"(a), "l"(b), "l"(c)); return d;
}

// ---------------- generic helpers ------------------------------------------
__device__ __forceinline__ uint32_t s2u(const void* p) {
    uint32_t a; asm("{ .reg .u64 t; cvta.to.shared.u64 t, %1; cvt.u32.u64 %0, t; }" : "=r"(a) : "l"(p)); return a;
}
__device__ __forceinline__ void cp16(uint32_t d, const void* s) {
    asm volatile("cp.async.cg.shared.global [%0], [%1], 16;" :: "r"(d), "l"(s));
}
__device__ __forceinline__ void cpcommit() { asm volatile("cp.async.commit_group;" ::: "memory"); }
__device__ __forceinline__ void cpwait1()  { asm volatile("cp.async.wait_group 1;" ::: "memory"); }
__device__ __forceinline__ void cpwait0()  { asm volatile("cp.async.wait_group 0;" ::: "memory"); }
__device__ __forceinline__ void ldsm4(uint32_t* r, uint32_t a) {
    asm volatile("ldmatrix.sync.aligned.m8n8.x4.shared.b16 {%0,%1,%2,%3}, [%4];"
                 : "=r"(r[0]), "=r"(r[1]), "=r"(r[2]), "=r"(r[3]) : "r"(a));
}
__device__ __forceinline__ void mma16816(float* d, const uint32_t* a, const uint32_t* b) {
    asm volatile("mma.sync.aligned.m16n8k16.row.col.f32.bf16.bf16.f32 "
                 "{%0,%1,%2,%3}, {%4,%5,%6,%7}, {%8,%9}, {%0,%1,%2,%3};"
                 : "+f"(d[0]), "+f"(d[1]), "+f"(d[2]), "+f"(d[3])
                 : "r"(a[0]), "r"(a[1]), "r"(a[2]), "r"(a[3]), "r"(b[0]), "r"(b[1]));
}

// ---------------- init -----------------------------------------------------
__global__ void k_init() { g_cnt = 0; g_rel = 0; }

// ---------------- Wh transpose (fp32, for scan) -----------------------------
__global__ void k_transpose(const float* __restrict__ src, float* __restrict__ dst) {
    __shared__ float tile[32][33];
    int l = blockIdx.z;
    const float* s = src + (size_t)l * (HID * HID);
    float* d = dst + (size_t)l * (HID * HID);
    int x = blockIdx.x * 32 + threadIdx.x;
    int y0 = blockIdx.y * 32;
    #pragma unroll
    for (int r = threadIdx.y; r < 32; r += 8)
        tile[r][threadIdx.x] = s[(size_t)(y0 + r) * HID + x];
    __syncthreads();
    int xo = y0 + threadIdx.x;
    int yo0 = blockIdx.x * 32;
    #pragma unroll
    for (int r = threadIdx.y; r < 32; r += 8)
        d[(size_t)(yo0 + r) * HID + xo] = tile[threadIdx.x][r];
}

// ---- weight transpose + bf16 split: dst[n][k]=hi, dst[n][1024+k]=lo --------
__global__ void k_splitW(const float* __restrict__ src, __nv_bfloat16* __restrict__ dst,
                         int nstride, int nrows, size_t srcLS, size_t dstLS) {
    src += (size_t)blockIdx.z * srcLS;
    dst += (size_t)blockIdx.z * dstLS;
    __shared__ float t[32][33];
    int tx = threadIdx.x, ty = threadIdx.y;
    int n0 = blockIdx.x * 32, k0 = blockIdx.y * 32;
    #pragma unroll
    for (int r = ty; r < 32; r += 8) {
        int n = n0 + tx, k = k0 + r;
        t[r][tx] = (n < nrows) ? src[(size_t)k * nstride + n] : 0.f;
    }
    __syncthreads();
    #pragma unroll
    for (int r = ty; r < 32; r += 8) {
        int n = n0 + r, k = k0 + tx;
        float a = t[tx][r];
        __nv_bfloat16 h = __float2bfloat16(a);
        __nv_bfloat16 lo = __float2bfloat16(a - __bfloat162float(h));
        dst[(size_t)n * KPACK + k]        = h;
        dst[(size_t)n * KPACK + 1024 + k] = lo;
    }
}

// ---- activation split (optionally embedding-gathered) ----------------------
__global__ void k_splitA(const float* __restrict__ src, const int* __restrict__ idx,
                         __nv_bfloat16* __restrict__ dst) {
    int i = blockIdx.x;
    const float* row = idx ? (src + (size_t)idx[i] * HID) : (src + (size_t)i * HID);
    int c0 = threadIdx.x * 4;
    float4 v = *(const float4*)(row + c0);
    __nv_bfloat16* d = dst + (size_t)i * KPACK;
    float a[4] = {v.x, v.y, v.z, v.w};
    #pragma unroll
    for (int j = 0; j < 4; j++) {
        __nv_bfloat16 h = __float2bfloat16(a[j]);
        __nv_bfloat16 lo = __float2bfloat16(a[j] - __bfloat162float(h));
        d[c0 + j]        = h;
        d[1024 + c0 + j] = lo;
    }
}

// ---------------- mma.sync bf16 split-3 GEMM --------------------------------
// C[M,N] = A2[M,2048] (hi|lo) x B2[Npad,2048]^T, virtual K' = 3*1024:
//   phase 0: Ah*Bh, phase 1: Al*Bh, phase 2: Ah*Bl. fp32 accumulation.
// CTA tile 128x128, BK=32, 8 warps of 64x32, double-buffered cp.async.
#define NSTAGE_TOT 96   // 3 phases * (1024/32)

__global__ __launch_bounds__(256, 2)
void k_gemm(const __nv_bfloat16* __restrict__ A, const __nv_bfloat16* __restrict__ B,
            const float* __restrict__ bias, float* __restrict__ C, int N) {
    __shared__ __align__(1024) __nv_bfloat16 sA[2][128 * 32];
    __shared__ __align__(1024) __nv_bfloat16 sB[2][128 * 32];

    const int tid = threadIdx.x, l = tid & 31, wid = tid >> 5;
    const int bx = blockIdx.x, by = blockIdx.y;
    const int wm = (wid & 1) * 64, wn = (wid >> 1) * 32;

    // ---- loader mapping: thread -> row r=tid/2, two 16B chunks ----
    const int lr = tid >> 1;                 // row within tile (0..127)
    const int lc0 = (tid & 1) * 2;           // first chunk (0 or 2)
    const int lsw = (lr >> 1) & 3;           // swizzle key
    const uint32_t so0 = lr * 64 + (((lc0 + 0) ^ lsw) << 4);
    const uint32_t so1 = lr * 64 + (((lc0 + 1) ^ lsw) << 4);
    const __nv_bfloat16* gA = A + (size_t)(by * 128 + lr) * KPACK + lc0 * 8;
    const __nv_bfloat16* gB = B + (size_t)(bx * 128 + lr) * KPACK + lc0 * 8;
    const uint32_t suA0 = s2u(sA[0]), suA1 = s2u(sA[1]);
    const uint32_t suB0 = s2u(sB[0]), suB1 = s2u(sB[1]);

    float acc[4][4][4];
    #pragma unroll
    for (int mt = 0; mt < 4; mt++)
        #pragma unroll
        for (int nt = 0; nt < 4; nt++)
            #pragma unroll
            for (int j = 0; j < 4; j++) acc[mt][nt][j] = 0.f;

#define LOADST(S, BUF)                                                        \
    {                                                                         \
        int p_ = (S) >> 5, ks_ = ((S) & 31) * 32;                             \
        int ao_ = ((p_ == 1) ? 1024 : 0) + ks_;                               \
        int bo_ = ((p_ == 2) ? 1024 : 0) + ks_;                               \
        uint32_t da_ = (BUF) ? suA1 : suA0, db_ = (BUF) ? suB1 : suB0;        \
        cp16(da_ + so0, gA + ao_);                                            \
        cp16(da_ + so1, gA + ao_ + 8);                                        \
        cp16(db_ + so0, gB + bo_);                                            \
        cp16(db_ + so1, gB + bo_ + 8);                                        \
    }

    LOADST(0, 0); cpcommit();
    LOADST(1, 1); cpcommit();
    cpwait1();
    __syncthreads();

    // ldmatrix lane addressing (constant per lane)
    const int arow = wm + (l & 15);              // + mt*16
    const int ach  = (l >> 4);                   // + 2*k16
    const int brow = wn + (l & 7) + ((l & 16) >> 1); // + {0,16}
    const int bch  = ((l >> 3) & 1);             // + 2*k16

    for (int s = 0; s < NSTAGE_TOT; s++) {
        const int buf = s & 1;
        const uint32_t bA = buf ? suA1 : suA0;
        const uint32_t bB = buf ? suB1 : suB0;

        #pragma unroll
        for (int k16 = 0; k16 < 2; k16++) {
            uint32_t aF[4][4], bF[4][2];
            #pragma unroll
            for (int mt = 0; mt < 4; mt++) {
                int r = arow + mt * 16;
                int ch = ach + 2 * k16;
                ldsm4(aF[mt], bA + r * 64 + (((ch ^ ((r >> 1) & 3))) << 4));
            }
            {
                int r = brow, ch = bch + 2 * k16;
                ldsm4(&bF[0][0], bB + r * 64 + (((ch ^ ((r >> 1) & 3))) << 4));
                r = brow + 16;
                ldsm4(&bF[2][0], bB + r * 64 + (((ch ^ ((r >> 1) & 3))) << 4));
            }
            #pragma unroll
            for (int mt = 0; mt < 4; mt++)
                #pragma unroll
                for (int nt = 0; nt < 4; nt++)
                    mma16816(acc[mt][nt], aF[mt], bF[nt]);
        }

        __syncthreads();
        if (s + 2 < NSTAGE_TOT) { LOADST(s + 2, buf); cpcommit(); cpwait1(); }
        else cpwait0();
        __syncthreads();
    }

    // ---- epilogue: bias + store ----
    const int erow = by * 128 + wm + (l >> 2);
    const int ecol0 = bx * 128 + wn + 2 * (l & 3);
    #pragma unroll
    for (int mt = 0; mt < 4; mt++) {
        int r0 = erow + mt * 16;
        float* c0p = C + (size_t)r0 * N;
        float* c1p = c0p + (size_t)8 * N;
        #pragma unroll
        for (int nt = 0; nt < 4; nt++) {
            int c = ecol0 + nt * 8;
            if (c < N) {
                float bx0 = __ldg(bias + c), bx1 = __ldg(bias + c + 1);
                *(float2*)(c0p + c) = make_float2(acc[mt][nt][0] + bx0, acc[mt][nt][1] + bx1);
                *(float2*)(c1p + c) = make_float2(acc[mt][nt][2] + bx0, acc[mt][nt][3] + bx1);
            }
        }
    }
#undef LOADST
}

// ---------------- grid barrier ---------------------------------------------
__device__ __forceinline__ void grid_barrier(unsigned rv) {
    __syncthreads();
    if (threadIdx.x == 0) {
        __threadfence();
        unsigned prev = atomicAdd(&g_cnt, 1);
        if (prev == gridDim.x - 1) {
            atomicExch(&g_cnt, 0);
            __threadfence();
            asm volatile("st.release.gpu.u32 [%0], %1;" :: "l"(&g_rel), "r"(rv) : "memory");
        } else {
            unsigned v;
            do {
                asm volatile("ld.acquire.gpu.u32 %0, [%1];" : "=r"(v) : "l"(&g_rel) : "memory");
            } while (v < rv);
        }
    }
    __syncthreads();
}

// ---------------- recurrent scan (unchanged, proven) ------------------------
__global__ __launch_bounds__(128)
void k_scan(const float* __restrict__ Xp, float* __restrict__ Hbuf,
            const float* __restrict__ WT, const float* __restrict__ hinit,
            float* __restrict__ finalOut, unsigned epoch0) {
    const int tid = threadIdx.x;
    const int jb = blockIdx.x * 8;
    const int r2 = tid >> 2, c2 = tid & 3;
    const int r0 = r2 << 1;
    const int j0 = jb + (c2 << 1);
    const float* w0p = WT + (size_t)j0 * HID;
    const float* w1p = w0p + HID;

    for (int t = 0; t < S_LEN; t++) {
        const float* Hp = t ? (Hbuf + (size_t)(t - 1) * ROWH) : hinit;
        const float* h0p = Hp + (size_t)r0 * HID;
        const float* h1p = h0p + HID;

        ull a00 = 0, a01 = 0, a10 = 0, a11 = 0;
        #pragma unroll 4
        for (int k = 0; k < HID; k += 4) {
            ulonglong2 ha = *(const ulonglong2*)(h0p + k);
            ulonglong2 hb = *(const ulonglong2*)(h1p + k);
            ulonglong2 wa = *(const ulonglong2*)(w0p + k);
            ulonglong2 wb = *(const ulonglong2*)(w1p + k);
            a00 = fma2(ha.x, wa.x, a00); a00 = fma2(ha.y, wa.y, a00);
            a01 = fma2(ha.x, wb.x, a01); a01 = fma2(ha.y, wb.y, a01);
            a10 = fma2(hb.x, wa.x, a10); a10 = fma2(hb.y, wa.y, a10);
            a11 = fma2(hb.x, wb.x, a11); a11 = fma2(hb.y, wb.y, a11);
        }
        float2 s00 = up(a00), s01 = up(a01), s10 = up(a10), s11 = up(a11);

        size_t xb = (size_t)t * ROWH + (size_t)r0 * HID + j0;
        float2 x0 = *(const float2*)(Xp + xb);
        float2 x1 = *(const float2*)(Xp + xb + HID);

        float h00 = tanhf(x0.x + s00.x + s00.y);
        float h01 = tanhf(x0.y + s01.x + s01.y);
        float h10 = tanhf(x1.x + s10.x + s10.y);
        float h11 = tanhf(x1.y + s11.x + s11.y);

        *(float2*)(Hbuf + xb)       = make_float2(h00, h01);
        *(float2*)(Hbuf + xb + HID) = make_float2(h10, h11);

        if (t == S_LEN - 1 && finalOut) {
            size_t fb = (size_t)r0 * HID + j0;
            *(float2*)(finalOut + fb)       = make_float2(h00, h01);
            *(float2*)(finalOut + fb + HID) = make_float2(h10, h11);
        }
        grid_barrier(epoch0 + (unsigned)t + 1);
    }
}

// ---------------- hidden_final epilogue -------------------------------------
__global__ void k_final(float* __restrict__ out) {
    int i = blockIdx.x * blockDim.x + threadIdx.x;
    if (i < ROWH) {
        out[LOGITS_ELEMS + i]        = g_hf0[i];
        out[LOGITS_ELEMS + ROWH + i] = g_H[(size_t)(S_LEN - 1) * ROWH + i];
    }
}

// ---------------- launcher ---------------------------------------------------
extern "C" void kernel_launch(void* const* d_in, const int* in_sizes, int n_in,
                              void* d_out, int out_size) {
    const int*   inputs = (const int*)d_in[0];
    const float* hidden = (const float*)d_in[1];
    const float* emb    = (const float*)d_in[2];
    const float* Wx     = (const float*)d_in[3];
    const float* Wh     = (const float*)d_in[4];
    const float* b      = (const float*)d_in[5];
    const float* Wo     = (const float*)d_in[6];
    const float* bo     = (const float*)d_in[7];
    float* out = (float*)d_out;

    float *pX = 0, *pH = 0, *pWhT = 0, *phf = 0;
    __nv_bfloat16 *pA2 = 0, *pWoT2 = 0, *pWxT2 = 0;
    cudaGetSymbolAddress((void**)&pX,    g_X);
    cudaGetSymbolAddress((void**)&pH,    g_H);
    cudaGetSymbolAddress((void**)&pWhT,  g_WhT);
    cudaGetSymbolAddress((void**)&phf,   g_hf0);
    cudaGetSymbolAddress((void**)&pA2,   g_A2);
    cudaGetSymbolAddress((void**)&pWoT2, g_WoT2);
    cudaGetSymbolAddress((void**)&pWxT2, g_WxT2);

    k_init<<<1, 1>>>();
    k_transpose<<<dim3(32, 32, 2), dim3(32, 8)>>>(Wh, pWhT);
    // weight splits (Wo padded to 10240 rows, zero-filled)
    k_splitW<<<dim3(VPAD / 32, 32, 1), dim3(32, 8)>>>(Wo, pWoT2, VOCAB, VOCAB, 0, 0);
    k_splitW<<<dim3(32, 32, 2), dim3(32, 8)>>>(Wx, pWxT2, HID, HID,
                                               (size_t)HID * HID, (size_t)HID * KPACK);
    // Xp0 = emb[inputs] @ Wx0 + b0
    k_splitA<<<SB, 256>>>(emb, inputs, pA2);
    k_gemm<<<dim3(8, 64), 256>>>(pA2, pWxT2, b, pX, HID);
    // h0 scan
    k_scan<<<128, 128>>>(pX, pH, pWhT, hidden, phf, 0u);
    // Xp1 = H0 @ Wx1 + b1
    k_splitA<<<SB, 256>>>(pH, nullptr, pA2);
    k_gemm<<<dim3(8, 64), 256>>>(pA2, pWxT2 + (size_t)HID * KPACK, b + HID, pX, HID);
    // h1 scan
    k_scan<<<128, 128>>>(pX, pH, pWhT + HID * HID, hidden + ROWH, nullptr, 128u);
    // logits = TOP @ Wo + bo
    k_splitA<<<SB, 256>>>(pH, nullptr, pA2);
    k_gemm<<<dim3(80, 64), 256>>>(pA2, pWoT2, bo, out, VOCAB);

    if (out_size >= LOGITS_ELEMS + HIDFIN_ELEMS)
        k_final<<<128, 512>>>(out);
}

// round 5
// speedup vs baseline: 2.3449x; 2.0149x over previous
#include <cuda_runtime.h>
#include <cuda_bf16.h>
#include <math.h>
#include <stdint.h>

// Problem constants
#define S_LEN 128
#define BATCH 64
#define HID   1024
#define VOCAB 10000
#define VPAD  10240
#define SB    8192
#define ROWH  65536
#define LOGITS_ELEMS 81920000
#define HIDFIN_ELEMS 131072
#define KPACK 2048               // [hi(1024) | lo(1024)] bf16 per row

typedef unsigned long long ull;

// ---------------- static scratch ------------------------------------------
__device__ float g_X[SB * HID];                       // Xp (fp32)
__device__ float g_H[SB * HID];                       // H states (fp32)
__device__ float g_WhT[2 * HID * HID];                // Wh^T fp32 (scan)
__device__ float g_hf0[ROWH];                         // layer-0 final hidden
__device__ __nv_bfloat16 g_A2[(size_t)SB * KPACK];    // split A
__device__ __nv_bfloat16 g_WoT2[(size_t)VPAD * KPACK];// split Wo^T (padded)
__device__ __nv_bfloat16 g_WxT2[2 * HID * KPACK];     // split Wx^T per layer
__device__ unsigned g_cnt, g_rel;

// ---------------- f32x2 helpers (scan) ------------------------------------
__device__ __forceinline__ float2 up(ull v) {
    float2 r; asm("mov.b64 {%0, %1}, %2;" : "=f"(r.x), "=f"(r.y) : "l"(v)); return r;
}
__device__ __forceinline__ ull fma2(ull a, ull b, ull c) {
    ull d; asm("fma.rn.f32x2 %0, %1, %2, %3;" : "=l"(d) : "l"(a), "l"(b), "l"(c)); return d;
}

// ---------------- generic helpers ------------------------------------------
__device__ __forceinline__ uint32_t s2u(const void* p) {
    uint32_t a; asm("{ .reg .u64 t; cvta.to.shared.u64 t, %1; cvt.u32.u64 %0, t; }" : "=r"(a) : "l"(p)); return a;
}
__device__ __forceinline__ void cp16(uint32_t d, const void* s) {
    asm volatile("cp.async.cg.shared.global [%0], [%1], 16;" :: "r"(d), "l"(s));
}
__device__ __forceinline__ void cpcommit() { asm volatile("cp.async.commit_group;" ::: "memory"); }
__device__ __forceinline__ void cpwait1()  { asm volatile("cp.async.wait_group 1;" ::: "memory"); }
__device__ __forceinline__ void cpwait0()  { asm volatile("cp.async.wait_group 0;" ::: "memory"); }
__device__ __forceinline__ void ldsm4(uint32_t* r, uint32_t a) {
    asm volatile("ldmatrix.sync.aligned.m8n8.x4.shared.b16 {%0,%1,%2,%3}, [%4];"
                 : "=r"(r[0]), "=r"(r[1]), "=r"(r[2]), "=r"(r[3]) : "r"(a));
}
__device__ __forceinline__ void mma16816(float* d, const uint32_t* a, const uint32_t* b) {
    asm volatile("mma.sync.aligned.m16n8k16.row.col.f32.bf16.bf16.f32 "
                 "{%0,%1,%2,%3}, {%4,%5,%6,%7}, {%8,%9}, {%0,%1,%2,%3};"
                 : "+f"(d[0]), "+f"(d[1]), "+f"(d[2]), "+f"(d[3])
                 : "r"(a[0]), "r"(a[1]), "r"(a[2]), "r"(a[3]), "r"(b[0]), "r"(b[1]));
}

// ---------------- init -----------------------------------------------------
__global__ void k_init() { g_cnt = 0; g_rel = 0; }

// ---------------- Wh transpose (fp32, for scan) -----------------------------
__global__ void k_transpose(const float* __restrict__ src, float* __restrict__ dst) {
    __shared__ float tile[32][33];
    int l = blockIdx.z;
    const float* s = src + (size_t)l * (HID * HID);
    float* d = dst + (size_t)l * (HID * HID);
    int x = blockIdx.x * 32 + threadIdx.x;
    int y0 = blockIdx.y * 32;
    #pragma unroll
    for (int r = threadIdx.y; r < 32; r += 8)
        tile[r][threadIdx.x] = s[(size_t)(y0 + r) * HID + x];
    __syncthreads();
    int xo = y0 + threadIdx.x;
    int yo0 = blockIdx.x * 32;
    #pragma unroll
    for (int r = threadIdx.y; r < 32; r += 8)
        d[(size_t)(yo0 + r) * HID + xo] = tile[threadIdx.x][r];
}

// ---- weight transpose + bf16 split: dst[n][k]=hi, dst[n][1024+k]=lo --------
__global__ void k_splitW(const float* __restrict__ src, __nv_bfloat16* __restrict__ dst,
                         int nstride, int nrows, size_t srcLS, size_t dstLS) {
    src += (size_t)blockIdx.z * srcLS;
    dst += (size_t)blockIdx.z * dstLS;
    __shared__ float t[32][33];
    int tx = threadIdx.x, ty = threadIdx.y;
    int n0 = blockIdx.x * 32, k0 = blockIdx.y * 32;
    #pragma unroll
    for (int r = ty; r < 32; r += 8) {
        int n = n0 + tx, k = k0 + r;
        t[r][tx] = (n < nrows) ? src[(size_t)k * nstride + n] : 0.f;
    }
    __syncthreads();
    #pragma unroll
    for (int r = ty; r < 32; r += 8) {
        int n = n0 + r, k = k0 + tx;
        float a = t[tx][r];
        __nv_bfloat16 h = __float2bfloat16(a);
        __nv_bfloat16 lo = __float2bfloat16(a - __bfloat162float(h));
        dst[(size_t)n * KPACK + k]        = h;
        dst[(size_t)n * KPACK + 1024 + k] = lo;
    }
}

// ---- activation split (optionally embedding-gathered) ----------------------
__global__ void k_splitA(const float* __restrict__ src, const int* __restrict__ idx,
                         __nv_bfloat16* __restrict__ dst) {
    int i = blockIdx.x;
    const float* row = idx ? (src + (size_t)idx[i] * HID) : (src + (size_t)i * HID);
    int c0 = threadIdx.x * 4;
    float4 v = *(const float4*)(row + c0);
    __nv_bfloat16* d = dst + (size_t)i * KPACK;
    float a[4] = {v.x, v.y, v.z, v.w};
    #pragma unroll
    for (int j = 0; j < 4; j++) {
        __nv_bfloat16 h = __float2bfloat16(a[j]);
        __nv_bfloat16 lo = __float2bfloat16(a[j] - __bfloat162float(h));
        d[c0 + j]        = h;
        d[1024 + c0 + j] = lo;
    }
}

// ---------------- mma.sync bf16 split-3 GEMM, 3-stage pipeline --------------
// C[M,N] = A2[M,2048] (hi|lo) x B2[Npad,2048]^T, virtual K' = 3*1024.
// CTA tile 128x128, BK=32, 8 warps of 64x32, 3-stage cp.async, 1 sync/stage.
#define NSTAGE_TOT 96   // 3 phases * (1024/32)
#define GSMEM 49152     // 6 * 8KB

__global__ __launch_bounds__(256, 2)
void k_gemm(const __nv_bfloat16* __restrict__ A, const __nv_bfloat16* __restrict__ B,
            const float* __restrict__ bias, float* __restrict__ C, int N) {
    extern __shared__ __align__(1024) char smem_raw[];
    const uint32_t suA = s2u(smem_raw);          // 3 x 8KB A buffers
    const uint32_t suB = suA + 24576;            // 3 x 8KB B buffers

    const int tid = threadIdx.x, l = tid & 31, wid = tid >> 5;
    const int bx = blockIdx.x, by = blockIdx.y;
    const int wm = (wid & 1) * 64, wn = (wid >> 1) * 32;

    // ---- loader mapping: thread -> row r=tid/2, two 16B chunks ----
    const int lr = tid >> 1;
    const int lc0 = (tid & 1) * 2;
    const int lsw = (lr >> 1) & 3;
    const uint32_t so0 = lr * 64 + (((lc0 + 0) ^ lsw) << 4);
    const uint32_t so1 = lr * 64 + (((lc0 + 1) ^ lsw) << 4);
    const __nv_bfloat16* gA = A + (size_t)(by * 128 + lr) * KPACK + lc0 * 8;
    const __nv_bfloat16* gB = B + (size_t)(bx * 128 + lr) * KPACK + lc0 * 8;

    float acc[4][4][4];
    #pragma unroll
    for (int mt = 0; mt < 4; mt++)
        #pragma unroll
        for (int nt = 0; nt < 4; nt++)
            #pragma unroll
            for (int j = 0; j < 4; j++) acc[mt][nt][j] = 0.f;

#define LOADST(S, BUF)                                                        \
    {                                                                         \
        int p_ = (S) >> 5, ks_ = ((S) & 31) * 32;                             \
        int ao_ = ((p_ == 1) ? 1024 : 0) + ks_;                               \
        int bo_ = ((p_ == 2) ? 1024 : 0) + ks_;                               \
        uint32_t da_ = suA + (BUF) * 8192, db_ = suB + (BUF) * 8192;          \
        cp16(da_ + so0, gA + ao_);                                            \
        cp16(da_ + so1, gA + ao_ + 8);                                        \
        cp16(db_ + so0, gB + bo_);                                            \
        cp16(db_ + so1, gB + bo_ + 8);                                        \
    }

    LOADST(0, 0); cpcommit();
    LOADST(1, 1); cpcommit();

    // ldmatrix lane addressing (constant per lane)
    const int arow = wm + (l & 15);
    const int ach  = (l >> 4);
    const int brow = wn + (l & 7) + ((l & 16) >> 1);
    const int bch  = ((l >> 3) & 1);

    int bufC = 0, bufL = 2;
    for (int s = 0; s < NSTAGE_TOT; s++) {
        if (s + 2 < NSTAGE_TOT) cpwait1(); else cpwait0();
        __syncthreads();
        if (s + 2 < NSTAGE_TOT) { LOADST(s + 2, bufL); cpcommit(); }

        const uint32_t bA = suA + bufC * 8192;
        const uint32_t bB = suB + bufC * 8192;

        #pragma unroll
        for (int k16 = 0; k16 < 2; k16++) {
            uint32_t aF[4][4], bF[4][2];
            #pragma unroll
            for (int mt = 0; mt < 4; mt++) {
                int r = arow + mt * 16;
                int ch = ach + 2 * k16;
                ldsm4(aF[mt], bA + r * 64 + (((ch ^ ((r >> 1) & 3))) << 4));
            }
            {
                int r = brow, ch = bch + 2 * k16;
                ldsm4(&bF[0][0], bB + r * 64 + (((ch ^ ((r >> 1) & 3))) << 4));
                r = brow + 16;
                ldsm4(&bF[2][0], bB + r * 64 + (((ch ^ ((r >> 1) & 3))) << 4));
            }
            #pragma unroll
            for (int mt = 0; mt < 4; mt++)
                #pragma unroll
                for (int nt = 0; nt < 4; nt++)
                    mma16816(acc[mt][nt], aF[mt], bF[nt]);
        }

        bufC = (bufC + 1 == 3) ? 0 : bufC + 1;
        bufL = (bufL + 1 == 3) ? 0 : bufL + 1;
    }

    // ---- epilogue: bias + store ----
    const int erow = by * 128 + wm + (l >> 2);
    const int ecol0 = bx * 128 + wn + 2 * (l & 3);
    #pragma unroll
    for (int mt = 0; mt < 4; mt++) {
        int r0 = erow + mt * 16;
        float* c0p = C + (size_t)r0 * N;
        float* c1p = c0p + (size_t)8 * N;
        #pragma unroll
        for (int nt = 0; nt < 4; nt++) {
            int c = ecol0 + nt * 8;
            if (c < N) {
                float bx0 = __ldg(bias + c), bx1 = __ldg(bias + c + 1);
                *(float2*)(c0p + c) = make_float2(acc[mt][nt][0] + bx0, acc[mt][nt][1] + bx1);
                *(float2*)(c1p + c) = make_float2(acc[mt][nt][2] + bx0, acc[mt][nt][3] + bx1);
            }
        }
    }
#undef LOADST
}

// ---------------- grid barrier ---------------------------------------------
__device__ __forceinline__ void grid_barrier(unsigned rv) {
    __syncthreads();
    if (threadIdx.x == 0) {
        __threadfence();
        unsigned prev = atomicAdd(&g_cnt, 1);
        if (prev == gridDim.x - 1) {
            atomicExch(&g_cnt, 0);
            __threadfence();
            asm volatile("st.release.gpu.u32 [%0], %1;" :: "l"(&g_rel), "r"(rv) : "memory");
        } else {
            unsigned v;
            do {
                asm volatile("ld.acquire.gpu.u32 %0, [%1];" : "=r"(v) : "l"(&g_rel) : "memory");
            } while (v < rv);
        }
    }
    __syncthreads();
}

// ---------------- recurrent scan: 512 thr, k-split-4, smem reduce -----------
// step t: H[t] = tanh( Xp[t] + H[t-1] @ Wh ).  Block: 8 j-cols x 64 rows.
__global__ __launch_bounds__(512)
void k_scan(const float* __restrict__ Xp, float* __restrict__ Hbuf,
            const float* __restrict__ WT, const float* __restrict__ hinit,
            float* __restrict__ finalOut, unsigned epoch0) {
    __shared__ __align__(16) float4 red[512];

    const int tid = threadIdx.x;
    const int kq = tid >> 7;             // k-quarter 0..3
    const int t7 = tid & 127;
    const int jb = blockIdx.x * 8;
    const int r2 = t7 >> 2, c2 = t7 & 3;
    const int r0 = r2 << 1;
    const int j0 = jb + (c2 << 1);
    const int k0 = kq << 8;              // 256-wide k slice
    const float* w0p = WT + (size_t)j0 * HID + k0;
    const float* w1p = w0p + HID;

    for (int t = 0; t < S_LEN; t++) {
        const float* Hp = t ? (Hbuf + (size_t)(t - 1) * ROWH) : hinit;
        const float* h0p = Hp + (size_t)r0 * HID + k0;
        const float* h1p = h0p + HID;

        ull a00 = 0, a01 = 0, a10 = 0, a11 = 0;
        #pragma unroll 4
        for (int k = 0; k < 256; k += 4) {
            ulonglong2 ha = *(const ulonglong2*)(h0p + k);
            ulonglong2 hb = *(const ulonglong2*)(h1p + k);
            ulonglong2 wa = *(const ulonglong2*)(w0p + k);
            ulonglong2 wb = *(const ulonglong2*)(w1p + k);
            a00 = fma2(ha.x, wa.x, a00); a00 = fma2(ha.y, wa.y, a00);
            a01 = fma2(ha.x, wb.x, a01); a01 = fma2(ha.y, wb.y, a01);
            a10 = fma2(hb.x, wa.x, a10); a10 = fma2(hb.y, wa.y, a10);
            a11 = fma2(hb.x, wb.x, a11); a11 = fma2(hb.y, wb.y, a11);
        }
        float2 s00 = up(a00), s01 = up(a01), s10 = up(a10), s11 = up(a11);
        red[tid] = make_float4(s00.x + s00.y, s01.x + s01.y,
                               s10.x + s10.y, s11.x + s11.y);
        __syncthreads();

        if (kq == 0) {
            float4 p0 = red[t7], p1 = red[128 + t7], p2 = red[256 + t7], p3 = red[384 + t7];
            size_t xb = (size_t)t * ROWH + (size_t)r0 * HID + j0;
            float2 x0 = *(const float2*)(Xp + xb);
            float2 x1 = *(const float2*)(Xp + xb + HID);

            float h00 = tanhf(x0.x + p0.x + p1.x + p2.x + p3.x);
            float h01 = tanhf(x0.y + p0.y + p1.y + p2.y + p3.y);
            float h10 = tanhf(x1.x + p0.z + p1.z + p2.z + p3.z);
            float h11 = tanhf(x1.y + p0.w + p1.w + p2.w + p3.w);

            *(float2*)(Hbuf + xb)       = make_float2(h00, h01);
            *(float2*)(Hbuf + xb + HID) = make_float2(h10, h11);

            if (t == S_LEN - 1 && finalOut) {
                size_t fb = (size_t)r0 * HID + j0;
                *(float2*)(finalOut + fb)       = make_float2(h00, h01);
                *(float2*)(finalOut + fb + HID) = make_float2(h10, h11);
            }
        }
        grid_barrier(epoch0 + (unsigned)t + 1);
    }
}

// ---------------- hidden_final epilogue -------------------------------------
__global__ void k_final(float* __restrict__ out) {
    int i = blockIdx.x * blockDim.x + threadIdx.x;
    if (i < ROWH) {
        out[LOGITS_ELEMS + i]        = g_hf0[i];
        out[LOGITS_ELEMS + ROWH + i] = g_H[(size_t)(S_LEN - 1) * ROWH + i];
    }
}

// ---------------- launcher ---------------------------------------------------
extern "C" void kernel_launch(void* const* d_in, const int* in_sizes, int n_in,
                              void* d_out, int out_size) {
    const int*   inputs = (const int*)d_in[0];
    const float* hidden = (const float*)d_in[1];
    const float* emb    = (const float*)d_in[2];
    const float* Wx     = (const float*)d_in[3];
    const float* Wh     = (const float*)d_in[4];
    const float* b      = (const float*)d_in[5];
    const float* Wo     = (const float*)d_in[6];
    const float* bo     = (const float*)d_in[7];
    float* out = (float*)d_out;

    float *pX = 0, *pH = 0, *pWhT = 0, *phf = 0;
    __nv_bfloat16 *pA2 = 0, *pWoT2 = 0, *pWxT2 = 0;
    cudaGetSymbolAddress((void**)&pX,    g_X);
    cudaGetSymbolAddress((void**)&pH,    g_H);
    cudaGetSymbolAddress((void**)&pWhT,  g_WhT);
    cudaGetSymbolAddress((void**)&phf,   g_hf0);
    cudaGetSymbolAddress((void**)&pA2,   g_A2);
    cudaGetSymbolAddress((void**)&pWoT2, g_WoT2);
    cudaGetSymbolAddress((void**)&pWxT2, g_WxT2);

    cudaFuncSetAttribute(k_gemm, cudaFuncAttributeMaxDynamicSharedMemorySize, GSMEM);

    // Order chosen so k_gemm lands at launch index 3 (ncu -s window).
    k_init<<<1, 1>>>();                                                   // 0
    k_splitW<<<dim3(32, 32, 2), dim3(32, 8)>>>(Wx, pWxT2, HID, HID,       // 1
                                               (size_t)HID * HID, (size_t)HID * KPACK);
    k_splitA<<<SB, 256>>>(emb, inputs, pA2);                              // 2
    k_gemm<<<dim3(8, 64), 256, GSMEM>>>(pA2, pWxT2, b, pX, HID);          // 3  Xp0
    k_transpose<<<dim3(32, 32, 2), dim3(32, 8)>>>(Wh, pWhT);              // 4
    k_splitW<<<dim3(VPAD / 32, 32, 1), dim3(32, 8)>>>(Wo, pWoT2, VOCAB, VOCAB, 0, 0); // 5
    k_scan<<<128, 512>>>(pX, pH, pWhT, hidden, phf, 0u);                  // 6  h0 scan
    k_splitA<<<SB, 256>>>(pH, nullptr, pA2);                              // 7
    k_gemm<<<dim3(8, 64), 256, GSMEM>>>(pA2, pWxT2 + (size_t)HID * KPACK, b + HID, pX, HID); // 8 Xp1
    k_scan<<<128, 512>>>(pX, pH, pWhT + HID * HID, hidden + ROWH, nullptr, 128u); // 9 h1 scan
    k_splitA<<<SB, 256>>>(pH, nullptr, pA2);                              // 10
    k_gemm<<<dim3(80, 64), 256, GSMEM>>>(pA2, pWoT2, bo, out, VOCAB);     // 11 logits
    if (out_size >= LOGITS_ELEMS + HIDFIN_ELEMS)
        k_final<<<128, 512>>>(out);                                       // 12
}

// round 6
// speedup vs baseline: 3.6977x; 1.5769x over previous
#include <cuda_runtime.h>
#include <cuda_bf16.h>
#include <math.h>
#include <stdint.h>

// Problem constants
#define S_LEN 128
#define BATCH 64
#define HID   1024
#define VOCAB 10000
#define VPAD  10240
#define SB    8192
#define ROWH  65536
#define LOGITS_ELEMS 81920000
#define HIDFIN_ELEMS 131072
#define KPACK 2048               // [hi(1024) | lo(1024)] bf16 per row

typedef unsigned long long ull;

// ---------------- static scratch ------------------------------------------
__device__ float g_X[SB * HID];                       // Xp (fp32)
__device__ float g_H[SB * HID];                       // H states (fp32)
__device__ float g_hf0[ROWH];                         // layer-0 final hidden
__device__ __nv_bfloat16 g_A2[(size_t)SB * KPACK];    // split A
__device__ __nv_bfloat16 g_WoT2[(size_t)VPAD * KPACK];// split Wo^T (padded)
__device__ __nv_bfloat16 g_WxT2[2 * HID * KPACK];     // split Wx^T per layer
__device__ unsigned g_cnt, g_rel;

// ---------------- f32x2 helpers (scan) ------------------------------------
__device__ __forceinline__ float2 up(ull v) {
    float2 r; asm("mov.b64 {%0, %1}, %2;" : "=f"(r.x), "=f"(r.y) : "l"(v)); return r;
}
__device__ __forceinline__ ull fma2(ull a, ull b, ull c) {
    ull d; asm("fma.rn.f32x2 %0, %1, %2, %3;" : "=l"(d) : "l"(a), "l"(b), "l"(c)); return d;
}

// ---------------- generic helpers ------------------------------------------
__device__ __forceinline__ uint32_t s2u(const void* p) {
    uint32_t a; asm("{ .reg .u64 t; cvta.to.shared.u64 t, %1; cvt.u32.u64 %0, t; }" : "=r"(a) : "l"(p)); return a;
}
__device__ __forceinline__ void cp16(uint32_t d, const void* s) {
    asm volatile("cp.async.cg.shared.global [%0], [%1], 16;" :: "r"(d), "l"(s));
}
__device__ __forceinline__ void cpcommit() { asm volatile("cp.async.commit_group;" ::: "memory"); }
__device__ __forceinline__ void cpwait1()  { asm volatile("cp.async.wait_group 1;" ::: "memory"); }
__device__ __forceinline__ void cpwait0()  { asm volatile("cp.async.wait_group 0;" ::: "memory"); }
__device__ __forceinline__ void ldsm4(uint32_t* r, uint32_t a) {
    asm volatile("ldmatrix.sync.aligned.m8n8.x4.shared.b16 {%0,%1,%2,%3}, [%4];"
                 : "=r"(r[0]), "=r"(r[1]), "=r"(r[2]), "=r"(r[3]) : "r"(a));
}
__device__ __forceinline__ void mma16816(float* d, const uint32_t* a, const uint32_t* b) {
    asm volatile("mma.sync.aligned.m16n8k16.row.col.f32.bf16.bf16.f32 "
                 "{%0,%1,%2,%3}, {%4,%5,%6,%7}, {%8,%9}, {%0,%1,%2,%3};"
                 : "+f"(d[0]), "+f"(d[1]), "+f"(d[2]), "+f"(d[3])
                 : "r"(a[0]), "r"(a[1]), "r"(a[2]), "r"(a[3]), "r"(b[0]), "r"(b[1]));
}

// ---- weight transpose + bf16 split: dst[n][k]=hi, dst[n][1024+k]=lo --------
// Block (0,0,0) thread (0,0) also resets the grid-barrier state (launch 0).
__global__ void k_splitW(const float* __restrict__ src, __nv_bfloat16* __restrict__ dst,
                         int nstride, int nrows, size_t srcLS, size_t dstLS) {
    if (threadIdx.x == 0 && threadIdx.y == 0 &&
        blockIdx.x == 0 && blockIdx.y == 0 && blockIdx.z == 0) {
        g_cnt = 0; g_rel = 0;
    }
    src += (size_t)blockIdx.z * srcLS;
    dst += (size_t)blockIdx.z * dstLS;
    __shared__ float t[32][33];
    int tx = threadIdx.x, ty = threadIdx.y;
    int n0 = blockIdx.x * 32, k0 = blockIdx.y * 32;
    #pragma unroll
    for (int r = ty; r < 32; r += 8) {
        int n = n0 + tx, k = k0 + r;
        t[r][tx] = (n < nrows) ? src[(size_t)k * nstride + n] : 0.f;
    }
    __syncthreads();
    #pragma unroll
    for (int r = ty; r < 32; r += 8) {
        int n = n0 + r, k = k0 + tx;
        float a = t[tx][r];
        __nv_bfloat16 h = __float2bfloat16(a);
        __nv_bfloat16 lo = __float2bfloat16(a - __bfloat162float(h));
        dst[(size_t)n * KPACK + k]        = h;
        dst[(size_t)n * KPACK + 1024 + k] = lo;
    }
}

// ---- activation split (optionally embedding-gathered) ----------------------
__global__ void k_splitA(const float* __restrict__ src, const int* __restrict__ idx,
                         __nv_bfloat16* __restrict__ dst) {
    int i = blockIdx.x;
    const float* row = idx ? (src + (size_t)idx[i] * HID) : (src + (size_t)i * HID);
    int c0 = threadIdx.x * 4;
    float4 v = *(const float4*)(row + c0);
    __nv_bfloat16* d = dst + (size_t)i * KPACK;
    float a[4] = {v.x, v.y, v.z, v.w};
    #pragma unroll
    for (int j = 0; j < 4; j++) {
        __nv_bfloat16 h = __float2bfloat16(a[j]);
        __nv_bfloat16 lo = __float2bfloat16(a[j] - __bfloat162float(h));
        d[c0 + j]        = h;
        d[1024 + c0 + j] = lo;
    }
}

// ---------------- mma.sync bf16 split-3 GEMM, 3-stage pipeline --------------
#define NSTAGE_TOT 96   // 3 phases * (1024/32)
#define GSMEM 49152     // 6 * 8KB

__global__ __launch_bounds__(256, 2)
void k_gemm(const __nv_bfloat16* __restrict__ A, const __nv_bfloat16* __restrict__ B,
            const float* __restrict__ bias, float* __restrict__ C, int N) {
    extern __shared__ __align__(1024) char smem_raw[];
    const uint32_t suA = s2u(smem_raw);          // 3 x 8KB A buffers
    const uint32_t suB = suA + 24576;            // 3 x 8KB B buffers

    const int tid = threadIdx.x, l = tid & 31, wid = tid >> 5;
    const int bx = blockIdx.x, by = blockIdx.y;
    const int wm = (wid & 1) * 64, wn = (wid >> 1) * 32;

    const int lr = tid >> 1;
    const int lc0 = (tid & 1) * 2;
    const int lsw = (lr >> 1) & 3;
    const uint32_t so0 = lr * 64 + (((lc0 + 0) ^ lsw) << 4);
    const uint32_t so1 = lr * 64 + (((lc0 + 1) ^ lsw) << 4);
    const __nv_bfloat16* gA = A + (size_t)(by * 128 + lr) * KPACK + lc0 * 8;
    const __nv_bfloat16* gB = B + (size_t)(bx * 128 + lr) * KPACK + lc0 * 8;

    float acc[4][4][4];
    #pragma unroll
    for (int mt = 0; mt < 4; mt++)
        #pragma unroll
        for (int nt = 0; nt < 4; nt++)
            #pragma unroll
            for (int j = 0; j < 4; j++) acc[mt][nt][j] = 0.f;

#define LOADST(S, BUF)                                                        \
    {                                                                         \
        int p_ = (S) >> 5, ks_ = ((S) & 31) * 32;                             \
        int ao_ = ((p_ == 1) ? 1024 : 0) + ks_;                               \
        int bo_ = ((p_ == 2) ? 1024 : 0) + ks_;                               \
        uint32_t da_ = suA + (BUF) * 8192, db_ = suB + (BUF) * 8192;          \
        cp16(da_ + so0, gA + ao_);                                            \
        cp16(da_ + so1, gA + ao_ + 8);                                        \
        cp16(db_ + so0, gB + bo_);                                            \
        cp16(db_ + so1, gB + bo_ + 8);                                        \
    }

    LOADST(0, 0); cpcommit();
    LOADST(1, 1); cpcommit();

    const int arow = wm + (l & 15);
    const int ach  = (l >> 4);
    const int brow = wn + (l & 7) + ((l & 16) >> 1);
    const int bch  = ((l >> 3) & 1);

    int bufC = 0, bufL = 2;
    for (int s = 0; s < NSTAGE_TOT; s++) {
        if (s + 2 < NSTAGE_TOT) cpwait1(); else cpwait0();
        __syncthreads();
        if (s + 2 < NSTAGE_TOT) { LOADST(s + 2, bufL); cpcommit(); }

        const uint32_t bA = suA + bufC * 8192;
        const uint32_t bB = suB + bufC * 8192;

        #pragma unroll
        for (int k16 = 0; k16 < 2; k16++) {
            uint32_t aF[4][4], bF[4][2];
            #pragma unroll
            for (int mt = 0; mt < 4; mt++) {
                int r = arow + mt * 16;
                int ch = ach + 2 * k16;
                ldsm4(aF[mt], bA + r * 64 + (((ch ^ ((r >> 1) & 3))) << 4));
            }
            {
                int r = brow, ch = bch + 2 * k16;
                ldsm4(&bF[0][0], bB + r * 64 + (((ch ^ ((r >> 1) & 3))) << 4));
                r = brow + 16;
                ldsm4(&bF[2][0], bB + r * 64 + (((ch ^ ((r >> 1) & 3))) << 4));
            }
            #pragma unroll
            for (int mt = 0; mt < 4; mt++)
                #pragma unroll
                for (int nt = 0; nt < 4; nt++)
                    mma16816(acc[mt][nt], aF[mt], bF[nt]);
        }

        bufC = (bufC + 1 == 3) ? 0 : bufC + 1;
        bufL = (bufL + 1 == 3) ? 0 : bufL + 1;
    }

    const int erow = by * 128 + wm + (l >> 2);
    const int ecol0 = bx * 128 + wn + 2 * (l & 3);
    #pragma unroll
    for (int mt = 0; mt < 4; mt++) {
        int r0 = erow + mt * 16;
        float* c0p = C + (size_t)r0 * N;
        float* c1p = c0p + (size_t)8 * N;
        #pragma unroll
        for (int nt = 0; nt < 4; nt++) {
            int c = ecol0 + nt * 8;
            if (c < N) {
                float bx0 = __ldg(bias + c), bx1 = __ldg(bias + c + 1);
                *(float2*)(c0p + c) = make_float2(acc[mt][nt][0] + bx0, acc[mt][nt][1] + bx1);
                *(float2*)(c1p + c) = make_float2(acc[mt][nt][2] + bx0, acc[mt][nt][3] + bx1);
            }
        }
    }
#undef LOADST
}

// ---------------- grid barrier (with backoff) -------------------------------
__device__ __forceinline__ void grid_barrier(unsigned rv) {
    __syncthreads();
    if (threadIdx.x == 0) {
        __threadfence();
        unsigned prev = atomicAdd(&g_cnt, 1);
        if (prev == gridDim.x - 1) {
            atomicExch(&g_cnt, 0);
            __threadfence();
            asm volatile("st.release.gpu.u32 [%0], %1;" :: "l"(&g_rel), "r"(rv) : "memory");
        } else {
            unsigned v;
            while (1) {
                asm volatile("ld.acquire.gpu.u32 %0, [%1];" : "=r"(v) : "l"(&g_rel) : "memory");
                if (v >= rv) break;
                asm volatile("nanosleep.u32 32;");
            }
        }
    }
    __syncthreads();
}

// ---------------- recurrent scan: W-slice in smem, 512 thr, k-split-4 -------
// step t: H[t] = tanh( Xp[t] + H[t-1] @ Wh ).  Block: 8 j-cols x 64 rows.
#define WSTR 1028   // padded col stride (floats): 4112B % 128 != 0 -> no bank clash

__global__ __launch_bounds__(512)
void k_scan(const float* __restrict__ Xp, float* __restrict__ Hbuf,
            const float* __restrict__ Wh, const float* __restrict__ hinit,
            float* __restrict__ finalOut, unsigned epoch0) {
    __shared__ __align__(16) float ws[8 * WSTR];
    __shared__ __align__(16) float4 red[512];

    const int tid = threadIdx.x;
    const int kq = tid >> 7;             // k-quarter 0..3
    const int t7 = tid & 127;
    const int jb = blockIdx.x * 8;
    const int r2 = t7 >> 2, c2 = t7 & 3;
    const int r0 = r2 << 1;
    const int j0 = jb + (c2 << 1);
    const int k0 = kq << 8;              // 256-wide k slice

    // one-time W slice load: ws[j][k] = Wh[k][jb+j]
    for (int idx = tid; idx < 8 * HID; idx += 512) {
        int j = idx & 7, k = idx >> 3;
        ws[j * WSTR + k] = Wh[(size_t)k * HID + jb + j];
    }
    __syncthreads();

    const float* w0p = ws + (size_t)(c2 << 1) * WSTR + k0;
    const float* w1p = w0p + WSTR;

    for (int t = 0; t < S_LEN; t++) {
        const float* Hp = t ? (Hbuf + (size_t)(t - 1) * ROWH) : hinit;
        const float* h0p = Hp + (size_t)r0 * HID + k0;
        const float* h1p = h0p + HID;

        ull a00 = 0, a01 = 0, a10 = 0, a11 = 0;
        #pragma unroll 4
        for (int k = 0; k < 256; k += 4) {
            ulonglong2 ha = *(const ulonglong2*)(h0p + k);
            ulonglong2 hb = *(const ulonglong2*)(h1p + k);
            ulonglong2 wa = *(const ulonglong2*)(w0p + k);
            ulonglong2 wb = *(const ulonglong2*)(w1p + k);
            a00 = fma2(ha.x, wa.x, a00); a00 = fma2(ha.y, wa.y, a00);
            a01 = fma2(ha.x, wb.x, a01); a01 = fma2(ha.y, wb.y, a01);
            a10 = fma2(hb.x, wa.x, a10); a10 = fma2(hb.y, wa.y, a10);
            a11 = fma2(hb.x, wb.x, a11); a11 = fma2(hb.y, wb.y, a11);
        }
        float2 s00 = up(a00), s01 = up(a01), s10 = up(a10), s11 = up(a11);
        red[tid] = make_float4(s00.x + s00.y, s01.x + s01.y,
                               s10.x + s10.y, s11.x + s11.y);
        __syncthreads();

        if (kq == 0) {
            float4 p0 = red[t7], p1 = red[128 + t7], p2 = red[256 + t7], p3 = red[384 + t7];
            size_t xb = (size_t)t * ROWH + (size_t)r0 * HID + j0;
            float2 x0 = *(const float2*)(Xp + xb);
            float2 x1 = *(const float2*)(Xp + xb + HID);

            float h00 = tanhf(x0.x + p0.x + p1.x + p2.x + p3.x);
            float h01 = tanhf(x0.y + p0.y + p1.y + p2.y + p3.y);
            float h10 = tanhf(x1.x + p0.z + p1.z + p2.z + p3.z);
            float h11 = tanhf(x1.y + p0.w + p1.w + p2.w + p3.w);

            *(float2*)(Hbuf + xb)       = make_float2(h00, h01);
            *(float2*)(Hbuf + xb + HID) = make_float2(h10, h11);

            if (t == S_LEN - 1 && finalOut) {
                size_t fb = (size_t)r0 * HID + j0;
                *(float2*)(finalOut + fb)       = make_float2(h00, h01);
                *(float2*)(finalOut + fb + HID) = make_float2(h10, h11);
            }
        }
        grid_barrier(epoch0 + (unsigned)t + 1);
    }
}

// ---------------- hidden_final epilogue -------------------------------------
__global__ void k_final(float* __restrict__ out) {
    int i = blockIdx.x * blockDim.x + threadIdx.x;
    if (i < ROWH) {
        out[LOGITS_ELEMS + i]        = g_hf0[i];
        out[LOGITS_ELEMS + ROWH + i] = g_H[(size_t)(S_LEN - 1) * ROWH + i];
    }
}

// ---------------- launcher ---------------------------------------------------
extern "C" void kernel_launch(void* const* d_in, const int* in_sizes, int n_in,
                              void* d_out, int out_size) {
    const int*   inputs = (const int*)d_in[0];
    const float* hidden = (const float*)d_in[1];
    const float* emb    = (const float*)d_in[2];
    const float* Wx     = (const float*)d_in[3];
    const float* Wh     = (const float*)d_in[4];
    const float* b      = (const float*)d_in[5];
    const float* Wo     = (const float*)d_in[6];
    const float* bo     = (const float*)d_in[7];
    float* out = (float*)d_out;

    float *pX = 0, *pH = 0, *phf = 0;
    __nv_bfloat16 *pA2 = 0, *pWoT2 = 0, *pWxT2 = 0;
    cudaGetSymbolAddress((void**)&pX,    g_X);
    cudaGetSymbolAddress((void**)&pH,    g_H);
    cudaGetSymbolAddress((void**)&phf,   g_hf0);
    cudaGetSymbolAddress((void**)&pA2,   g_A2);
    cudaGetSymbolAddress((void**)&pWoT2, g_WoT2);
    cudaGetSymbolAddress((void**)&pWxT2, g_WxT2);

    cudaFuncSetAttribute(k_gemm, cudaFuncAttributeMaxDynamicSharedMemorySize, GSMEM);

    // Launch order chosen so k_scan (h0) lands at index 3 (ncu -s window).
    k_splitW<<<dim3(32, 32, 2), dim3(32, 8)>>>(Wx, pWxT2, HID, HID,            // 0 (+barrier init)
                                               (size_t)HID * HID, (size_t)HID * KPACK);
    k_splitA<<<SB, 256>>>(emb, inputs, pA2);                                   // 1
    k_gemm<<<dim3(8, 64), 256, GSMEM>>>(pA2, pWxT2, b, pX, HID);               // 2  Xp0
    k_scan<<<128, 512>>>(pX, pH, Wh, hidden, phf, 0u);                         // 3  h0 scan  <- ncu
    k_splitW<<<dim3(VPAD / 32, 32, 1), dim3(32, 8)>>>(Wo, pWoT2, VOCAB, VOCAB, 0, 0); // 4
    k_splitA<<<SB, 256>>>(pH, nullptr, pA2);                                   // 5
    k_gemm<<<dim3(8, 64), 256, GSMEM>>>(pA2, pWxT2 + (size_t)HID * KPACK, b + HID, pX, HID); // 6 Xp1
    k_scan<<<128, 512>>>(pX, pH, Wh + HID * HID, hidden + ROWH, nullptr, 128u); // 7 h1 scan
    k_splitA<<<SB, 256>>>(pH, nullptr, pA2);                                   // 8
    k_gemm<<<dim3(80, 64), 256, GSMEM>>>(pA2, pWoT2, bo, out, VOCAB);          // 9 logits
    if (out_size >= LOGITS_ELEMS + HIDFIN_ELEMS)
        k_final<<<128, 512>>>(out);                                            // 10
}

// round 9
// speedup vs baseline: 3.7618x; 1.0173x over previous
#include <cuda_runtime.h>
#include <cuda_bf16.h>
#include <math.h>
#include <stdint.h>

// Problem constants
#define S_LEN 128
#define BATCH 64
#define HID   1024
#define VOCAB 10000
#define VPAD  10240
#define SB    8192
#define ROWH  65536
#define LOGITS_ELEMS 81920000
#define HIDFIN_ELEMS 131072
#define KPACK 2048               // [hi(1024) | lo(1024)] bf16 per row

typedef unsigned long long ull;

// ---------------- static scratch ------------------------------------------
__device__ float g_X[SB * HID];                       // Xp (fp32)
__device__ float g_H[SB * HID];                       // H states (fp32)
__device__ float g_hf0[ROWH];                         // layer-0 final hidden
__device__ __nv_bfloat16 g_A2[(size_t)SB * KPACK];    // split A
__device__ __nv_bfloat16 g_WoT2[(size_t)VPAD * KPACK];// split Wo^T (padded)
__device__ __nv_bfloat16 g_WxT2[2 * HID * KPACK];     // split Wx^T per layer
__device__ unsigned g_cnt, g_rel;

// ---------------- f32x2 helpers (scan) ------------------------------------
__device__ __forceinline__ float2 up(ull v) {
    float2 r; asm("mov.b64 {%0, %1}, %2;" : "=f"(r.x), "=f"(r.y) : "l"(v)); return r;
}
__device__ __forceinline__ ull fma2(ull a, ull b, ull c) {
    ull d; asm("fma.rn.f32x2 %0, %1, %2, %3;" : "=l"(d) : "l"(a), "l"(b), "l"(c)); return d;
}

// ---------------- generic helpers ------------------------------------------
__device__ __forceinline__ uint32_t s2u(const void* p) {
    uint32_t a; asm("{ .reg .u64 t; cvta.to.shared.u64 t, %1; cvt.u32.u64 %0, t; }" : "=r"(a) : "l"(p)); return a;
}
__device__ __forceinline__ void cp16(uint32_t d, const void* s) {
    asm volatile("cp.async.cg.shared.global [%0], [%1], 16;" :: "r"(d), "l"(s));
}
__device__ __forceinline__ void cpcommit() { asm volatile("cp.async.commit_group;" ::: "memory"); }
__device__ __forceinline__ void cpwait1()  { asm volatile("cp.async.wait_group 1;" ::: "memory"); }
__device__ __forceinline__ void cpwait0()  { asm volatile("cp.async.wait_group 0;" ::: "memory"); }
__device__ __forceinline__ void ldsm4(uint32_t* r, uint32_t a) {
    asm volatile("ldmatrix.sync.aligned.m8n8.x4.shared.b16 {%0,%1,%2,%3}, [%4];"
                 : "=r"(r[0]), "=r"(r[1]), "=r"(r[2]), "=r"(r[3]) : "r"(a));
}
__device__ __forceinline__ void mma16816(float* d, const uint32_t* a, const uint32_t* b) {
    asm volatile("mma.sync.aligned.m16n8k16.row.col.f32.bf16.bf16.f32 "
                 "{%0,%1,%2,%3}, {%4,%5,%6,%7}, {%8,%9}, {%0,%1,%2,%3};"
                 : "+f"(d[0]), "+f"(d[1]), "+f"(d[2]), "+f"(d[3])
                 : "r"(a[0]), "r"(a[1]), "r"(a[2]), "r"(a[3]), "r"(b[0]), "r"(b[1]));
}

// ---- weight transpose + bf16 split: dst[n][k]=hi, dst[n][1024+k]=lo --------
// Block (0,0,0) thread (0,0) also resets the grid-barrier state (launch 0).
__global__ void k_splitW(const float* __restrict__ src, __nv_bfloat16* __restrict__ dst,
                         int nstride, int nrows, size_t srcLS, size_t dstLS) {
    if (threadIdx.x == 0 && threadIdx.y == 0 &&
        blockIdx.x == 0 && blockIdx.y == 0 && blockIdx.z == 0) {
        g_cnt = 0; g_rel = 0;
    }
    src += (size_t)blockIdx.z * srcLS;
    dst += (size_t)blockIdx.z * dstLS;
    __shared__ float t[32][33];
    int tx = threadIdx.x, ty = threadIdx.y;
    int n0 = blockIdx.x * 32, k0 = blockIdx.y * 32;
    #pragma unroll
    for (int r = ty; r < 32; r += 8) {
        int n = n0 + tx, k = k0 + r;
        t[r][tx] = (n < nrows) ? src[(size_t)k * nstride + n] : 0.f;
    }
    __syncthreads();
    #pragma unroll
    for (int r = ty; r < 32; r += 8) {
        int n = n0 + r, k = k0 + tx;
        float a = t[tx][r];
        __nv_bfloat16 h = __float2bfloat16(a);
        __nv_bfloat16 lo = __float2bfloat16(a - __bfloat162float(h));
        dst[(size_t)n * KPACK + k]        = h;
        dst[(size_t)n * KPACK + 1024 + k] = lo;
    }
}

// ---- activation split (embedding-gathered; used only for Xp0 input) --------
__global__ void k_splitA(const float* __restrict__ src, const int* __restrict__ idx,
                         __nv_bfloat16* __restrict__ dst) {
    int i = blockIdx.x;
    const float* row = idx ? (src + (size_t)idx[i] * HID) : (src + (size_t)i * HID);
    int c0 = threadIdx.x * 4;
    float4 v = *(const float4*)(row + c0);
    __nv_bfloat16* d = dst + (size_t)i * KPACK;
    float a[4] = {v.x, v.y, v.z, v.w};
    #pragma unroll
    for (int j = 0; j < 4; j++) {
        __nv_bfloat16 h = __float2bfloat16(a[j]);
        __nv_bfloat16 lo = __float2bfloat16(a[j] - __bfloat162float(h));
        d[c0 + j]        = h;
        d[1024 + c0 + j] = lo;
    }
}

// ---------------- mma.sync bf16 split-3 GEMM, 3-stage pipeline --------------
#define NSTAGE_TOT 96   // 3 phases * (1024/32)
#define GSMEM 49152     // 6 * 8KB

__global__ __launch_bounds__(256, 2)
void k_gemm(const __nv_bfloat16* __restrict__ A, const __nv_bfloat16* __restrict__ B,
            const float* __restrict__ bias, float* __restrict__ C, int N) {
    extern __shared__ __align__(1024) char smem_raw[];
    const uint32_t suA = s2u(smem_raw);          // 3 x 8KB A buffers
    const uint32_t suB = suA + 24576;            // 3 x 8KB B buffers

    const int tid = threadIdx.x, l = tid & 31, wid = tid >> 5;
    const int bx = blockIdx.x, by = blockIdx.y;
    const int wm = (wid & 1) * 64, wn = (wid >> 1) * 32;

    const int lr = tid >> 1;
    const int lc0 = (tid & 1) * 2;
    const int lsw = (lr >> 1) & 3;
    const uint32_t so0 = lr * 64 + (((lc0 + 0) ^ lsw) << 4);
    const uint32_t so1 = lr * 64 + (((lc0 + 1) ^ lsw) << 4);
    const __nv_bfloat16* gA = A + (size_t)(by * 128 + lr) * KPACK + lc0 * 8;
    const __nv_bfloat16* gB = B + (size_t)(bx * 128 + lr) * KPACK + lc0 * 8;

    float acc[4][4][4];
    #pragma unroll
    for (int mt = 0; mt < 4; mt++)
        #pragma unroll
        for (int nt = 0; nt < 4; nt++)
            #pragma unroll
            for (int j = 0; j < 4; j++) acc[mt][nt][j] = 0.f;

#define LOADST(S, BUF)                                                        \
    {                                                                         \
        int p_ = (S) >> 5, ks_ = ((S) & 31) * 32;                             \
        int ao_ = ((p_ == 1) ? 1024 : 0) + ks_;                               \
        int bo_ = ((p_ == 2) ? 1024 : 0) + ks_;                               \
        uint32_t da_ = suA + (BUF) * 8192, db_ = suB + (BUF) * 8192;          \
        cp16(da_ + so0, gA + ao_);                                            \
        cp16(da_ + so1, gA + ao_ + 8);                                        \
        cp16(db_ + so0, gB + bo_);                                            \
        cp16(db_ + so1, gB + bo_ + 8);                                        \
    }

    LOADST(0, 0); cpcommit();
    LOADST(1, 1); cpcommit();

    const int arow = wm + (l & 15);
    const int ach  = (l >> 4);
    const int brow = wn + (l & 7) + ((l & 16) >> 1);
    const int bch  = ((l >> 3) & 1);

    int bufC = 0, bufL = 2;
    for (int s = 0; s < NSTAGE_TOT; s++) {
        if (s + 2 < NSTAGE_TOT) cpwait1(); else cpwait0();
        __syncthreads();
        if (s + 2 < NSTAGE_TOT) { LOADST(s + 2, bufL); cpcommit(); }

        const uint32_t bA = suA + bufC * 8192;
        const uint32_t bB = suB + bufC * 8192;

        #pragma unroll
        for (int k16 = 0; k16 < 2; k16++) {
            uint32_t aF[4][4], bF[4][2];
            #pragma unroll
            for (int mt = 0; mt < 4; mt++) {
                int r = arow + mt * 16;
                int ch = ach + 2 * k16;
                ldsm4(aF[mt], bA + r * 64 + (((ch ^ ((r >> 1) & 3))) << 4));
            }
            {
                int r = brow, ch = bch + 2 * k16;
                ldsm4(&bF[0][0], bB + r * 64 + (((ch ^ ((r >> 1) & 3))) << 4));
                r = brow + 16;
                ldsm4(&bF[2][0], bB + r * 64 + (((ch ^ ((r >> 1) & 3))) << 4));
            }
            #pragma unroll
            for (int mt = 0; mt < 4; mt++)
                #pragma unroll
                for (int nt = 0; nt < 4; nt++)
                    mma16816(acc[mt][nt], aF[nt == 0 ? mt : mt], bF[nt]);
        }

        bufC = (bufC + 1 == 3) ? 0 : bufC + 1;
        bufL = (bufL + 1 == 3) ? 0 : bufL + 1;
    }

    const int erow = by * 128 + wm + (l >> 2);
    const int ecol0 = bx * 128 + wn + 2 * (l & 3);
    #pragma unroll
    for (int mt = 0; mt < 4; mt++) {
        int r0 = erow + mt * 16;
        float* c0p = C + (size_t)r0 * N;
        float* c1p = c0p + (size_t)8 * N;
        #pragma unroll
        for (int nt = 0; nt < 4; nt++) {
            int c = ecol0 + nt * 8;
            if (c < N) {
                float bx0 = __ldg(bias + c), bx1 = __ldg(bias + c + 1);
                *(float2*)(c0p + c) = make_float2(acc[mt][nt][0] + bx0, acc[mt][nt][1] + bx1);
                *(float2*)(c1p + c) = make_float2(acc[mt][nt][2] + bx0, acc[mt][nt][3] + bx1);
            }
        }
    }
#undef LOADST
}

// ---------------- grid barrier (identical to R6) ----------------------------
__device__ __forceinline__ void grid_barrier(unsigned rv) {
    __syncthreads();
    if (threadIdx.x == 0) {
        __threadfence();
        unsigned prev = atomicAdd(&g_cnt, 1);
        if (prev == gridDim.x - 1) {
            atomicExch(&g_cnt, 0);
            __threadfence();
            asm volatile("st.release.gpu.u32 [%0], %1;" :: "l"(&g_rel), "r"(rv) : "memory");
        } else {
            unsigned v;
            while (1) {
                asm volatile("ld.acquire.gpu.u32 %0, [%1];" : "=r"(v) : "l"(&g_rel) : "memory");
                if (v >= rv) break;
                asm volatile("nanosleep.u32 32;");
            }
        }
    }
    __syncthreads();
}

// ---------------- recurrent scan: prefetched H, fused bf16-split output -----
// step t: H[t] = tanh( Xp[t] + H[t-1] @ Wh ).  Block: 8 j-cols x 64 rows.
// Inner loop double-buffers 16-k chunks of H in registers (8 LDG.128 in flight).
// Epilogue also writes bf16 hi/lo split rows into A2out (GEMM input fusion).
#define WSTR 1028   // padded col stride (floats)

__global__ __launch_bounds__(512)
void k_scan(const float* __restrict__ Xp, float* __restrict__ Hbuf,
            const float* __restrict__ Wh, const float* __restrict__ hinit,
            float* __restrict__ finalOut, __nv_bfloat16* __restrict__ A2out,
            unsigned epoch0) {
    __shared__ __align__(16) float ws[8 * WSTR];
    __shared__ __align__(16) float4 red[512];

    const int tid = threadIdx.x;
    const int kq = tid >> 7;             // k-quarter 0..3
    const int t7 = tid & 127;
    const int jb = blockIdx.x * 8;
    const int r2 = t7 >> 2, c2 = t7 & 3;
    const int r0 = r2 << 1;
    const int j0 = jb + (c2 << 1);
    const int k0 = kq << 8;              // 256-wide k slice

    // one-time W slice load: ws[j][k] = Wh[k][jb+j]
    for (int idx = tid; idx < 8 * HID; idx += 512) {
        int j = idx & 7, k = idx >> 3;
        ws[j * WSTR + k] = Wh[(size_t)k * HID + jb + j];
    }
    __syncthreads();

    const float* w0p = ws + (size_t)(c2 << 1) * WSTR + k0;
    const float* w1p = w0p + WSTR;

    for (int t = 0; t < S_LEN; t++) {
        const float* Hp = t ? (Hbuf + (size_t)(t - 1) * ROWH) : hinit;
        const float* h0p = Hp + (size_t)r0 * HID + k0;
        const float* h1p = h0p + HID;

        // prefetch Xp[t] early (independent of H[t-1])
        size_t xb = (size_t)t * ROWH + (size_t)r0 * HID + j0;
        float2 x0 = *(const float2*)(Xp + xb);
        float2 x1 = *(const float2*)(Xp + xb + HID);

        ull a00 = 0, a01 = 0, a10 = 0, a11 = 0;

        // double-buffered 16-k chunks: 8 LDG.128 in flight while FMAing prev
        ulonglong2 pa[4], pb[4];
        #pragma unroll
        for (int i = 0; i < 4; i++) {
            pa[i] = *(const ulonglong2*)(h0p + 4 * i);
            pb[i] = *(const ulonglong2*)(h1p + 4 * i);
        }
        #pragma unroll
        for (int kc = 0; kc < 256; kc += 16) {
            ulonglong2 na[4], nb[4];
            if (kc + 16 < 256) {
                #pragma unroll
                for (int i = 0; i < 4; i++) {
                    na[i] = *(const ulonglong2*)(h0p + kc + 16 + 4 * i);
                    nb[i] = *(const ulonglong2*)(h1p + kc + 16 + 4 * i);
                }
            }
            #pragma unroll
            for (int i = 0; i < 4; i++) {
                int k = kc + 4 * i;
                ulonglong2 wa = *(const ulonglong2*)(w0p + k);
                ulonglong2 wb = *(const ulonglong2*)(w1p + k);
                a00 = fma2(pa[i].x, wa.x, a00); a00 = fma2(pa[i].y, wa.y, a00);
                a01 = fma2(pa[i].x, wb.x, a01); a01 = fma2(pa[i].y, wb.y, a01);
                a10 = fma2(pb[i].x, wa.x, a10); a10 = fma2(pb[i].y, wa.y, a10);
                a11 = fma2(pb[i].x, wb.x, a11); a11 = fma2(pb[i].y, wb.y, a11);
            }
            #pragma unroll
            for (int i = 0; i < 4; i++) { pa[i] = na[i]; pb[i] = nb[i]; }
        }

        float2 s00 = up(a00), s01 = up(a01), s10 = up(a10), s11 = up(a11);
        red[tid] = make_float4(s00.x + s00.y, s01.x + s01.y,
                               s10.x + s10.y, s11.x + s11.y);
        __syncthreads();

        if (kq == 0) {
            float4 p0 = red[t7], p1 = red[128 + t7], p2 = red[256 + t7], p3 = red[384 + t7];

            float h00 = tanhf(x0.x + p0.x + p1.x + p2.x + p3.x);
            float h01 = tanhf(x0.y + p0.y + p1.y + p2.y + p3.y);
            float h10 = tanhf(x1.x + p0.z + p1.z + p2.z + p3.z);
            float h11 = tanhf(x1.y + p0.w + p1.w + p2.w + p3.w);

            *(float2*)(Hbuf + xb)       = make_float2(h00, h01);
            *(float2*)(Hbuf + xb + HID) = make_float2(h10, h11);

            // fused bf16 hi/lo split (GEMM A input)
            {
                size_t ar0 = ((size_t)t * BATCH + r0) * KPACK;
                size_t ar1 = ar0 + KPACK;
                __nv_bfloat16 e00 = __float2bfloat16(h00);
                __nv_bfloat16 e01 = __float2bfloat16(h01);
                __nv_bfloat16 e10 = __float2bfloat16(h10);
                __nv_bfloat16 e11 = __float2bfloat16(h11);
                __nv_bfloat162 hi0; hi0.x = e00; hi0.y = e01;
                __nv_bfloat162 hi1; hi1.x = e10; hi1.y = e11;
                __nv_bfloat162 lo0, lo1;
                lo0.x = __float2bfloat16(h00 - __bfloat162float(e00));
                lo0.y = __float2bfloat16(h01 - __bfloat162float(e01));
                lo1.x = __float2bfloat16(h10 - __bfloat162float(e10));
                lo1.y = __float2bfloat16(h11 - __bfloat162float(e11));
                *(__nv_bfloat162*)(A2out + ar0 + j0)        = hi0;
                *(__nv_bfloat162*)(A2out + ar0 + 1024 + j0) = lo0;
                *(__nv_bfloat162*)(A2out + ar1 + j0)        = hi1;
                *(__nv_bfloat162*)(A2out + ar1 + 1024 + j0) = lo1;
            }

            if (t == S_LEN - 1 && finalOut) {
                size_t fb = (size_t)r0 * HID + j0;
                *(float2*)(finalOut + fb)       = make_float2(h00, h01);
                *(float2*)(finalOut + fb + HID) = make_float2(h10, h11);
            }
        }
        grid_barrier(epoch0 + (unsigned)t + 1);
    }
}

// ---------------- hidden_final epilogue -------------------------------------
__global__ void k_final(float* __restrict__ out) {
    int i = blockIdx.x * blockDim.x + threadIdx.x;
    if (i < ROWH) {
        out[LOGITS_ELEMS + i]        = g_hf0[i];
        out[LOGITS_ELEMS + ROWH + i] = g_H[(size_t)(S_LEN - 1) * ROWH + i];
    }
}

// ---------------- launcher ---------------------------------------------------
extern "C" void kernel_launch(void* const* d_in, const int* in_sizes, int n_in,
                              void* d_out, int out_size) {
    const int*   inputs = (const int*)d_in[0];
    const float* hidden = (const float*)d_in[1];
    const float* emb    = (const float*)d_in[2];
    const float* Wx     = (const float*)d_in[3];
    const float* Wh     = (const float*)d_in[4];
    const float* b      = (const float*)d_in[5];
    const float* Wo     = (const float*)d_in[6];
    const float* bo     = (const float*)d_in[7];
    float* out = (float*)d_out;

    float *pX = 0, *pH = 0, *phf = 0;
    __nv_bfloat16 *pA2 = 0, *pWoT2 = 0, *pWxT2 = 0;
    cudaGetSymbolAddress((void**)&pX,    g_X);
    cudaGetSymbolAddress((void**)&pH,    g_H);
    cudaGetSymbolAddress((void**)&phf,   g_hf0);
    cudaGetSymbolAddress((void**)&pA2,   g_A2);
    cudaGetSymbolAddress((void**)&pWoT2, g_WoT2);
    cudaGetSymbolAddress((void**)&pWxT2, g_WxT2);

    cudaFuncSetAttribute(k_gemm, cudaFuncAttributeMaxDynamicSharedMemorySize, GSMEM);

    // Launch order keeps k_scan (h0) at index 3 (ncu -s window).
    k_splitW<<<dim3(32, 32, 2), dim3(32, 8)>>>(Wx, pWxT2, HID, HID,            // 0 (+barrier init)
                                               (size_t)HID * HID, (size_t)HID * KPACK);
    k_splitA<<<SB, 256>>>(emb, inputs, pA2);                                   // 1
    k_gemm<<<dim3(8, 64), 256, GSMEM>>>(pA2, pWxT2, b, pX, HID);               // 2  Xp0
    k_scan<<<128, 512>>>(pX, pH, Wh, hidden, phf, pA2, 0u);                    // 3  h0 scan  <- ncu
    k_splitW<<<dim3(VPAD / 32, 32, 1), dim3(32, 8)>>>(Wo, pWoT2, VOCAB, VOCAB, 0, 0); // 4
    k_gemm<<<dim3(8, 64), 256, GSMEM>>>(pA2, pWxT2 + (size_t)HID * KPACK, b + HID, pX, HID); // 5 Xp1
    k_scan<<<128, 512>>>(pX, pH, Wh + HID * HID, hidden + ROWH, nullptr, pA2, 128u); // 6 h1 scan
    k_gemm<<<dim3(80, 64), 256, GSMEM>>>(pA2, pWoT2, bo, out, VOCAB);          // 7 logits
    if (out_size >= LOGITS_ELEMS + HIDFIN_ELEMS)
        k_final<<<128, 512>>>(out);                                            // 8
}